// round 4
// baseline (speedup 1.0000x reference)
#include <cuda_runtime.h>
#include <cstdint>

#define OUTP 7
#define CCH 256
#define NS 14                        // samples per axis
#define BINS 49
#define OUT_PER_BOX (CCH * BINS)     // 12544
#define CH_PER_CTA 16
#define NGROUPS (CCH / CH_PER_CTA)   // 16
#define THREADS 256
#define NWARPS (THREADS / 32)        // 8
#define PIX_CAP 784                  // 28 rows x 28 cols max after dedupe
#define PSTRIDE 18                   // floats per pixel (16 ch + pad, float2-aligned)
#define TAPSTRIDE 17                 // int2 per bin (16 taps + pad, bank-spread)
#define NBIN_PAD 52                  // 13 j-groups * 4 bins

__global__ __launch_bounds__(THREADS) void roi_pooler_kernel(
    const float* __restrict__ f0, const float* __restrict__ f1,
    const float* __restrict__ f2, const float* __restrict__ f3,
    const float* __restrict__ boxes, float* __restrict__ out)
{
    extern __shared__ float s_patch[];          // PIX_CAP * PSTRIDE floats (56448 B)

    __shared__ int2  s_tap[NBIN_PAD * TAPSTRIDE];     // (byte offset, weight)
    __shared__ float s_out[CH_PER_CTA * BINS];        // 784
    __shared__ float s_wy0[NS], s_wy1[NS], s_wx0[NS], s_wx1[NS];
    __shared__ int   s_yl[NS], s_yh[NS], s_xl[NS], s_xh[NS];
    __shared__ int   s_rslo[NS], s_rshi[NS], s_cslo[NS], s_cshi[NS];
    __shared__ int   s_rowoffW[2 * NS];               // nrow entries: row * W
    __shared__ int   s_colval[2 * NS];                // ncol entries
    __shared__ int   s_nrow, s_ncol;
    __shared__ float s_x1, s_y1, s_bw, s_bh, s_Hf, s_Wf;
    __shared__ int   s_W, s_HW;
    __shared__ const float* s_base;

    const int blk = blockIdx.x;             // [0, 512*16)
    const int n   = blk >> 4;               // box index
    const int g   = blk & (NGROUPS - 1);    // channel group
    const int tid = threadIdx.x;
    const int lane = tid & 31;
    const int wid  = tid >> 5;

    // ---- A: box geometry (thread 0) ----
    if (tid == 0) {
        const int b = n >> 8;
        const float bx1 = boxes[n * 4 + 0];
        const float by1 = boxes[n * 4 + 1];
        const float bx2 = boxes[n * 4 + 2];
        const float by2 = boxes[n * 4 + 3];
        const float area = (bx2 - bx1) * (by2 - by1);
        float lvlf = floorf(4.0f + log2f(sqrtf(area) * (1.0f / 224.0f) + 1e-8f));
        lvlf = fminf(fmaxf(lvlf, 2.0f), 5.0f);
        const int lvl = (int)lvlf - 2;

        int H, W; float scale; const float* fp;
        switch (lvl) {
            case 0:  H = 200; W = 200; scale = 0.25f;    fp = f0; break;
            case 1:  H = 100; W = 100; scale = 0.125f;   fp = f1; break;
            case 2:  H = 50;  W = 50;  scale = 0.0625f;  fp = f2; break;
            default: H = 25;  W = 25;  scale = 0.03125f; fp = f3; break;
        }
        const float x1s = bx1 * scale, y1s = by1 * scale;
        const float x2s = bx2 * scale, y2s = by2 * scale;
        const float roi_w = fmaxf(x2s - x1s, 1.0f);
        const float roi_h = fmaxf(y2s - y1s, 1.0f);
        s_x1 = x1s;  s_y1 = y1s;
        s_bw = roi_w * (1.0f / OUTP);
        s_bh = roi_h * (1.0f / OUTP);
        s_Hf = (float)H;  s_Wf = (float)W;
        s_W  = W;  s_HW = H * W;
        s_base = fp + ((size_t)b * CCH + (size_t)g * CH_PER_CTA) * H * W;
    }
    __syncthreads();

    // ---- B: 28 sample preps (torchvision ROIAlign aligned=False) ----
    if (tid < 2 * NS) {
        const bool is_y = tid < NS;
        const int  i    = is_y ? tid : tid - NS;
        const int  p    = i >> 1;
        const int  s    = i & 1;
        const float gg  = (float)p + ((float)s + 0.5f) * 0.5f;
        const float coord = is_y ? (s_y1 + s_bh * gg) : (s_x1 + s_bw * gg);
        const float lim   = is_y ? s_Hf : s_Wf;

        const float v  = (coord > -1.0f && coord < lim) ? 1.0f : 0.0f;
        float cc  = fmaxf(coord, 0.0f);
        float low = floorf(cc);
        const float cap = lim - 1.0f;
        const bool at_edge = (low >= cap);
        low = fminf(low, cap);
        const float high = fminf(low + 1.0f, cap);
        if (at_edge) cc = low;
        const float frac = cc - low;
        const float w0 = (1.0f - frac) * v;
        const float w1 = frac * v;

        if (is_y) {
            s_yl[i] = (int)low;  s_yh[i] = (int)high;
            s_wy0[i] = w0;       s_wy1[i] = w1;
        } else {
            s_xl[i] = (int)low;  s_xh[i] = (int)high;
            s_wx0[i] = w0;       s_wx1[i] = w1;
        }
    }
    __syncthreads();

    // ---- C: dedupe row taps and col taps (threads 0 and 1, both sorted asc) ----
    if (tid == 0) {
        const int W = s_W;
        int ia = 0, ib = 0, cnt = 0, last = -0x40000000;
        while (ia < NS || ib < NS) {
            const int va = (ia < NS) ? s_yl[ia] : 0x7fffffff;
            const int vb = (ib < NS) ? s_yh[ib] : 0x7fffffff;
            if (va <= vb) {
                if (va != last) { last = va; s_rowoffW[cnt] = va * W; cnt++; }
                s_rslo[ia] = cnt - 1; ia++;
            } else {
                if (vb != last) { last = vb; s_rowoffW[cnt] = vb * W; cnt++; }
                s_rshi[ib] = cnt - 1; ib++;
            }
        }
        s_nrow = cnt;
    } else if (tid == 32) {
        int ia = 0, ib = 0, cnt = 0, last = -0x40000000;
        while (ia < NS || ib < NS) {
            const int va = (ia < NS) ? s_xl[ia] : 0x7fffffff;
            const int vb = (ib < NS) ? s_xh[ib] : 0x7fffffff;
            if (va <= vb) {
                if (va != last) { last = va; s_colval[cnt] = va; cnt++; }
                s_cslo[ia] = cnt - 1; ia++;
            } else {
                if (vb != last) { last = vb; s_colval[cnt] = vb; cnt++; }
                s_cshi[ib] = cnt - 1; ib++;
            }
        }
        s_ncol = cnt;
    }
    __syncthreads();

    const int nrow = s_nrow;
    const int ncol = s_ncol;

    // ---- D1: build per-bin tap table (pixel byte offset, weight) ----
    for (int e = tid; e < NBIN_PAD * 16; e += THREADS) {
        const int bin = e >> 4;
        const int t   = e & 15;
        int off = 0; float w = 0.0f;
        if (bin < BINS) {
            const int ph = bin / OUTP;
            const int pw = bin - ph * OUTP;
            const int sy = t >> 3;
            const int sx = (t >> 2) & 1;
            const int qy = (t >> 1) & 1;
            const int qx = t & 1;
            const int iy = 2 * ph + sy;
            const int ix = 2 * pw + sx;
            const int rs = qy ? s_rshi[iy] : s_rslo[iy];
            const int cs = qx ? s_cshi[ix] : s_cslo[ix];
            const float wy = qy ? s_wy1[iy] : s_wy0[iy];
            const float wx = qx ? s_wx1[ix] : s_wx0[ix];
            w = wy * wx;
            off = (rs * ncol + cs) * (PSTRIDE * 4);   // byte offset into patch
        }
        s_tap[bin * TAPSTRIDE + t] = make_int2(off, __float_as_int(w));
    }

    // ---- D2: stage patch: patch[pixel][channel], 16 channels ----
    {
        const float* const base = s_base;
        const int HW = s_HW;
        for (int ch = wid; ch < CH_PER_CTA; ch += NWARPS) {
            const float* const fch = base + (size_t)ch * HW;
            for (int rs = 0; rs < nrow; ++rs) {
                const float* const frow = fch + s_rowoffW[rs];
                const int pbase = rs * ncol;
                for (int cs = lane; cs < ncol; cs += 32) {
                    s_patch[(pbase + cs) * PSTRIDE + ch] = frow[s_colval[cs]];
                }
            }
        }
    }
    __syncthreads();

    // ---- E: compute. warp = 4 bins x 8 lanes; lane owns a channel pair ----
    {
        const int c2    = lane & 7;        // channel pair index: ch = 2*c2, 2*c2+1
        const int which = lane >> 3;       // 0..3
        const char* const pc = (const char*)s_patch + c2 * 8;

        #pragma unroll 1
        for (int j = wid; j < 13; j += NWARPS) {
            const int bin = 4 * j + which;
            const int2* const tp = s_tap + bin * TAPSTRIDE;
            float ax0 = 0.0f, ay0 = 0.0f, ax1 = 0.0f, ay1 = 0.0f;
            #pragma unroll
            for (int t = 0; t < 16; t += 2) {
                const int2 tw0 = tp[t];
                const int2 tw1 = tp[t + 1];
                const float2 v0 = *(const float2*)(pc + tw0.x);
                const float2 v1 = *(const float2*)(pc + tw1.x);
                const float w0 = __int_as_float(tw0.y);
                const float w1 = __int_as_float(tw1.y);
                ax0 = fmaf(w0, v0.x, ax0);
                ay0 = fmaf(w0, v0.y, ay0);
                ax1 = fmaf(w1, v1.x, ax1);
                ay1 = fmaf(w1, v1.y, ay1);
            }
            if (bin < BINS) {
                s_out[(2 * c2 + 0) * BINS + bin] = (ax0 + ax1) * 0.25f;
                s_out[(2 * c2 + 1) * BINS + bin] = (ay0 + ay1) * 0.25f;
            }
        }
    }
    __syncthreads();

    // ---- F: coalesced writeout ----
    {
        float* const out_g = out + (size_t)n * OUT_PER_BOX + (size_t)g * CH_PER_CTA * BINS;
        #pragma unroll
        for (int i = tid; i < CH_PER_CTA * BINS; i += THREADS) {
            out_g[i] = s_out[i];
        }
    }
}

extern "C" void kernel_launch(void* const* d_in, const int* in_sizes, int n_in,
                              void* d_out, int out_size) {
    const float* f0    = (const float*)d_in[0];
    const float* f1    = (const float*)d_in[1];
    const float* f2    = (const float*)d_in[2];
    const float* f3    = (const float*)d_in[3];
    const float* boxes = (const float*)d_in[4];
    float* out = (float*)d_out;

    const int dyn_smem = PIX_CAP * PSTRIDE * sizeof(float);   // 56448 B
    cudaFuncSetAttribute(roi_pooler_kernel,
                         cudaFuncAttributeMaxDynamicSharedMemorySize, dyn_smem);
    roi_pooler_kernel<<<512 * NGROUPS, THREADS, dyn_smem>>>(f0, f1, f2, f3, boxes, out);
}

// round 5
// speedup vs baseline: 1.3855x; 1.3855x over previous
#include <cuda_runtime.h>
#include <cstdint>

#define OUTP 7
#define CCH 256
#define NS 14                         // samples per axis
#define BINS 49
#define OUT_PER_BOX (CCH * BINS)      // 12544
#define CH_PER_CTA 8
#define NGROUPS (CCH / CH_PER_CTA)    // 32
#define THREADS 256
#define NWARPS (THREADS / 32)
#define PIX_PER_CH 1152               // worst-case padded patch < 1065 floats
#define OUT_PER_CTA (CH_PER_CTA * BINS)  // 392

__global__ __launch_bounds__(THREADS) void roi_pooler_kernel(
    const float* __restrict__ f0, const float* __restrict__ f1,
    const float* __restrict__ f2, const float* __restrict__ f3,
    const float* __restrict__ boxes, float* __restrict__ out)
{
    extern __shared__ float s_patch[];     // CH_PER_CTA * PIX_PER_CH floats (36864 B)

    __shared__ float4 s_yp[NS];            // (bits(rowoff_lo), bits(rowoff_hi), wy0, wy1)
    __shared__ float4 s_xp[NS];            // (bits(col_lo),   bits(col_hi),   wx0, wx1)
    __shared__ int   s_yl[NS], s_yh[NS], s_xl[NS], s_xh[NS];
    __shared__ float s_w0y[NS], s_w1y[NS], s_w0x[NS], s_w1x[NS];
    __shared__ float s_x1, s_y1, s_bw, s_bh, s_Hf, s_Wf;
    __shared__ int   s_W, s_HW;
    __shared__ int   s_r0, s_c0, s_nrow, s_ncol, s_rowstride, s_chstride;
    __shared__ const float* s_base;

    const int blk  = blockIdx.x;             // [0, 512*NGROUPS)
    const int n    = blk >> 5;               // box index
    const int g    = blk & (NGROUPS - 1);    // channel group
    const int tid  = threadIdx.x;
    const int lane = tid & 31;
    const int wid  = tid >> 5;

    // ---- A: box geometry ----
    if (tid == 0) {
        const int b = n >> 8;
        const float bx1 = boxes[n * 4 + 0];
        const float by1 = boxes[n * 4 + 1];
        const float bx2 = boxes[n * 4 + 2];
        const float by2 = boxes[n * 4 + 3];
        const float area = (bx2 - bx1) * (by2 - by1);
        float lvlf = floorf(4.0f + log2f(sqrtf(area) * (1.0f / 224.0f) + 1e-8f));
        lvlf = fminf(fmaxf(lvlf, 2.0f), 5.0f);
        const int lvl = (int)lvlf - 2;

        int H, W; float scale; const float* fp;
        switch (lvl) {
            case 0:  H = 200; W = 200; scale = 0.25f;    fp = f0; break;
            case 1:  H = 100; W = 100; scale = 0.125f;   fp = f1; break;
            case 2:  H = 50;  W = 50;  scale = 0.0625f;  fp = f2; break;
            default: H = 25;  W = 25;  scale = 0.03125f; fp = f3; break;
        }
        const float x1s = bx1 * scale, y1s = by1 * scale;
        const float x2s = bx2 * scale, y2s = by2 * scale;
        s_x1 = x1s;  s_y1 = y1s;
        s_bw = fmaxf(x2s - x1s, 1.0f) * (1.0f / OUTP);
        s_bh = fmaxf(y2s - y1s, 1.0f) * (1.0f / OUTP);
        s_Hf = (float)H;  s_Wf = (float)W;
        s_W = W;  s_HW = H * W;
        s_base = fp + ((size_t)b * CCH + (size_t)g * CH_PER_CTA) * H * W;
    }
    __syncthreads();

    // ---- B: 28 sample preps (torchvision ROIAlign aligned=False) ----
    if (tid < 2 * NS) {
        const bool is_y = tid < NS;
        const int  i    = is_y ? tid : tid - NS;
        const int  p    = i >> 1;
        const int  s    = i & 1;
        const float gg  = (float)p + ((float)s + 0.5f) * 0.5f;
        const float coord = is_y ? (s_y1 + s_bh * gg) : (s_x1 + s_bw * gg);
        const float lim   = is_y ? s_Hf : s_Wf;

        const float v  = (coord > -1.0f && coord < lim) ? 1.0f : 0.0f;
        float cc  = fmaxf(coord, 0.0f);
        float low = floorf(cc);
        const float cap = lim - 1.0f;
        const bool at_edge = (low >= cap);
        low = fminf(low, cap);
        const float high = fminf(low + 1.0f, cap);
        if (at_edge) cc = low;
        const float frac = cc - low;
        const float w0 = (1.0f - frac) * v;
        const float w1 = frac * v;

        if (is_y) {
            s_yl[i] = (int)low;  s_yh[i] = (int)high;
            s_w0y[i] = w0;       s_w1y[i] = w1;
        } else {
            s_xl[i] = (int)low;  s_xh[i] = (int)high;
            s_w0x[i] = w0;       s_w1x[i] = w1;
        }
    }
    __syncthreads();

    // ---- C: bbox (O(1); sample coords are monotone in index) ----
    if (tid == 0) {
        const int r0 = s_yl[0], c0 = s_xl[0];
        const int nrow = s_yh[NS - 1] - r0 + 1;
        const int ncol = s_xh[NS - 1] - c0 + 1;
        s_r0 = r0;  s_c0 = c0;
        s_nrow = nrow;  s_ncol = ncol;
        s_rowstride = ncol + 1;
        s_chstride  = nrow * (ncol + 1);
    }
    __syncthreads();

    const int r0 = s_r0, c0 = s_c0;
    const int nrow = s_nrow, ncol = s_ncol;
    const int rowstride = s_rowstride;
    const int chstride  = s_chstride;

    // ---- D: pack per-sample params with local offsets ----
    if (tid < 2 * NS) {
        const bool is_y = tid < NS;
        const int  i    = is_y ? tid : tid - NS;
        if (is_y) {
            s_yp[i] = make_float4(__int_as_float((s_yl[i] - r0) * rowstride),
                                  __int_as_float((s_yh[i] - r0) * rowstride),
                                  s_w0y[i], s_w1y[i]);
        } else {
            s_xp[i] = make_float4(__int_as_float(s_xl[i] - c0),
                                  __int_as_float(s_xh[i] - c0),
                                  s_w0x[i], s_w1x[i]);
        }
    }

    // ---- E: stage patch (coalesced): warp per (ch,row) task ----
    {
        const float* const base = s_base + (size_t)r0 * s_W + c0;
        const int HW = s_HW, W = s_W;
        for (int t = wid; t < CH_PER_CTA * nrow; t += NWARPS) {
            const int ch = t / nrow;
            const int r  = t - ch * nrow;
            const float* const src = base + (size_t)ch * HW + r * W;
            float* const dst = s_patch + ch * chstride + r * rowstride;
            for (int c = lane; c < ncol; c += 32) dst[c] = src[c];
        }
    }
    __syncthreads();

    // ---- F: compute: thread per (channel, bin), gathers from smem ----
    float* const out_g = out + (size_t)n * OUT_PER_BOX + (size_t)g * OUT_PER_CTA;

    #pragma unroll
    for (int it = 0; it < 2; ++it) {
        const int idx = it * THREADS + tid;
        if (idx < OUT_PER_CTA) {
            const int c   = idx / BINS;
            const int bin = idx - c * BINS;
            const int ph  = bin / OUTP;
            const int pw  = bin - ph * OUTP;

            const float* const pc = s_patch + c * chstride;

            const float4 yp0 = s_yp[2 * ph + 0];
            const float4 yp1 = s_yp[2 * ph + 1];
            const float4 xp0 = s_xp[2 * pw + 0];
            const float4 xp1 = s_xp[2 * pw + 1];

            const float* const ra0 = pc + __float_as_int(yp0.x);
            const float* const rb0 = pc + __float_as_int(yp0.y);
            const float* const ra1 = pc + __float_as_int(yp1.x);
            const float* const rb1 = pc + __float_as_int(yp1.y);
            const int cl0 = __float_as_int(xp0.x), ch0 = __float_as_int(xp0.y);
            const int cl1 = __float_as_int(xp1.x), ch1 = __float_as_int(xp1.y);

            float acc;
            {   // sy=0, sx=0
                const float t0 = xp0.z * ra0[cl0] + xp0.w * ra0[ch0];
                const float t1 = xp0.z * rb0[cl0] + xp0.w * rb0[ch0];
                acc = yp0.z * t0 + yp0.w * t1;
            }
            {   // sy=0, sx=1
                const float t0 = xp1.z * ra0[cl1] + xp1.w * ra0[ch1];
                const float t1 = xp1.z * rb0[cl1] + xp1.w * rb0[ch1];
                acc += yp0.z * t0 + yp0.w * t1;
            }
            {   // sy=1, sx=0
                const float t0 = xp0.z * ra1[cl0] + xp0.w * ra1[ch0];
                const float t1 = xp0.z * rb1[cl0] + xp0.w * rb1[ch0];
                acc += yp1.z * t0 + yp1.w * t1;
            }
            {   // sy=1, sx=1
                const float t0 = xp1.z * ra1[cl1] + xp1.w * ra1[ch1];
                const float t1 = xp1.z * rb1[cl1] + xp1.w * rb1[ch1];
                acc += yp1.z * t0 + yp1.w * t1;
            }
            out_g[idx] = acc * 0.25f;
        }
    }
}

extern "C" void kernel_launch(void* const* d_in, const int* in_sizes, int n_in,
                              void* d_out, int out_size) {
    const float* f0    = (const float*)d_in[0];
    const float* f1    = (const float*)d_in[1];
    const float* f2    = (const float*)d_in[2];
    const float* f3    = (const float*)d_in[3];
    const float* boxes = (const float*)d_in[4];
    float* out = (float*)d_out;

    const int dyn_smem = CH_PER_CTA * PIX_PER_CH * sizeof(float);   // 36864 B
    cudaFuncSetAttribute(roi_pooler_kernel,
                         cudaFuncAttributeMaxDynamicSharedMemorySize, dyn_smem);
    roi_pooler_kernel<<<512 * NGROUPS, THREADS, dyn_smem>>>(f0, f1, f2, f3, boxes, out);
}

// round 6
// speedup vs baseline: 7.9901x; 5.7667x over previous
#include <cuda_runtime.h>
#include <cstdint>

#define OUTP 7
#define CCH 256
#define NS 14                        // samples per axis
#define BINS 49
#define OUT_PER_BOX (CCH * BINS)     // 12544
#define CH_PER_CTA 32
#define NGROUPS (CCH / CH_PER_CTA)   // 8
#define THREADS 256
#define NWARPS (THREADS / 32)        // 8 warps -> 8*4 = 32 channels

__global__ __launch_bounds__(THREADS) void roi_pooler_kernel(
    const float* __restrict__ f0, const float* __restrict__ f1,
    const float* __restrict__ f2, const float* __restrict__ f3,
    const float* __restrict__ boxes, float* __restrict__ out)
{
    // Per-ph packed y-params: 4 row offsets (already *W) and 4 weights
    __shared__ int4   s_ro[OUTP];
    __shared__ float4 s_wy[OUTP];
    // Per-lane x-tap: column index and x-weight (validity folded in). 32 padded.
    __shared__ int    s_col[32];
    __shared__ float  s_wxw[32];
    __shared__ float  s_x1, s_y1, s_bw, s_bh, s_Hf, s_Wf;
    __shared__ int    s_W, s_HW;
    __shared__ const float* s_base;

    const int blk  = blockIdx.x;             // [0, 512*NGROUPS)
    const int n    = blk >> 3;               // box index [0,512)
    const int g    = blk & (NGROUPS - 1);    // channel group [0,8)
    const int tid  = threadIdx.x;
    const int lane = tid & 31;
    const int wid  = tid >> 5;

    // ---- A: box geometry ----
    if (tid == 0) {
        const int b = n >> 8;
        const float bx1 = boxes[n * 4 + 0];
        const float by1 = boxes[n * 4 + 1];
        const float bx2 = boxes[n * 4 + 2];
        const float by2 = boxes[n * 4 + 3];
        const float area = (bx2 - bx1) * (by2 - by1);
        float lvlf = floorf(4.0f + log2f(sqrtf(area) * (1.0f / 224.0f) + 1e-8f));
        lvlf = fminf(fmaxf(lvlf, 2.0f), 5.0f);
        const int lvl = (int)lvlf - 2;

        int H, W; float scale; const float* fp;
        switch (lvl) {
            case 0:  H = 200; W = 200; scale = 0.25f;    fp = f0; break;
            case 1:  H = 100; W = 100; scale = 0.125f;   fp = f1; break;
            case 2:  H = 50;  W = 50;  scale = 0.0625f;  fp = f2; break;
            default: H = 25;  W = 25;  scale = 0.03125f; fp = f3; break;
        }
        const float x1s = bx1 * scale, y1s = by1 * scale;
        const float x2s = bx2 * scale, y2s = by2 * scale;
        s_x1 = x1s;  s_y1 = y1s;
        s_bw = fmaxf(x2s - x1s, 1.0f) * (1.0f / OUTP);
        s_bh = fmaxf(y2s - y1s, 1.0f) * (1.0f / OUTP);
        s_Hf = (float)H;  s_Wf = (float)W;
        s_W = W;  s_HW = H * W;
        s_base = fp + ((size_t)b * CCH + (size_t)g * CH_PER_CTA) * H * W;
    }
    __syncthreads();

    // ---- B: 28 sample preps (torchvision ROIAlign aligned=False) ----
    if (tid < 2 * NS) {
        const bool is_y = tid < NS;
        const int  i    = is_y ? tid : tid - NS;
        const int  p    = i >> 1;
        const int  s    = i & 1;
        const float gg  = (float)p + ((float)s + 0.5f) * 0.5f;
        const float coord = is_y ? (s_y1 + s_bh * gg) : (s_x1 + s_bw * gg);
        const float lim   = is_y ? s_Hf : s_Wf;

        const float v  = (coord > -1.0f && coord < lim) ? 1.0f : 0.0f;
        float cc  = fmaxf(coord, 0.0f);
        float low = floorf(cc);
        const float cap = lim - 1.0f;
        const bool at_edge = (low >= cap);
        low = fminf(low, cap);
        const float high = fminf(low + 1.0f, cap);
        if (at_edge) cc = low;
        const float frac = cc - low;
        const float w0 = (1.0f - frac) * v;
        const float w1 = frac * v;

        if (is_y) {
            // sample i belongs to ph = i>>1, sub-sample s = i&1
            // components: 4*ph + 2*s + {0,1} = {lo,hi}
            const int W = s_W;
            int*   rop = (int*)s_ro;
            float* wyp = (float*)s_wy;
            rop[4 * (i >> 1) + 2 * (i & 1) + 0] = (int)low  * W;
            rop[4 * (i >> 1) + 2 * (i & 1) + 1] = (int)high * W;
            wyp[4 * (i >> 1) + 2 * (i & 1) + 0] = w0;
            wyp[4 * (i >> 1) + 2 * (i & 1) + 1] = w1;
        } else {
            // x tap j = 2*i + q; lane j handles bin pw = j>>2
            s_col[2 * i + 0] = (int)low;
            s_col[2 * i + 1] = (int)high;
            s_wxw[2 * i + 0] = w0;
            s_wxw[2 * i + 1] = w1;
        }
    }
    if (tid < 4) {            // pad lanes 28..31: zero weight, valid address
        s_col[28 + tid] = 0;
        s_wxw[28 + tid] = 0.0f;
    }
    __syncthreads();

    // ---- C: compute. warp = 4 channels; lanes = 28 x-taps (4 per bin pw) ----
    const int   colb = s_col[lane];
    const float wxwb = s_wxw[lane];
    const int   HW   = s_HW;
    const float* const base0 = s_base + (size_t)(wid * 4) * HW + colb;
    float* const out_g = out + (size_t)n * OUT_PER_BOX
                             + (size_t)g * CH_PER_CTA * BINS
                             + (size_t)(wid * 4) * BINS;

    const bool writer = ((lane & 3) == 0) && (lane < 28);
    const int  pw     = lane >> 2;

    #pragma unroll 1
    for (int ph = 0; ph < OUTP; ++ph) {
        const int4   ro = s_ro[ph];
        const float4 wy = s_wy[ph];

        float r0, r1, r2, r3;
        {
            const float* p = base0;
            float a = wxwb * (wy.x * p[ro.x] + wy.y * p[ro.y] +
                              wy.z * p[ro.z] + wy.w * p[ro.w]);
            a += __shfl_xor_sync(0xffffffffu, a, 1);
            a += __shfl_xor_sync(0xffffffffu, a, 2);
            r0 = a;
        }
        {
            const float* p = base0 + HW;
            float a = wxwb * (wy.x * p[ro.x] + wy.y * p[ro.y] +
                              wy.z * p[ro.z] + wy.w * p[ro.w]);
            a += __shfl_xor_sync(0xffffffffu, a, 1);
            a += __shfl_xor_sync(0xffffffffu, a, 2);
            r1 = a;
        }
        {
            const float* p = base0 + 2 * HW;
            float a = wxwb * (wy.x * p[ro.x] + wy.y * p[ro.y] +
                              wy.z * p[ro.z] + wy.w * p[ro.w]);
            a += __shfl_xor_sync(0xffffffffu, a, 1);
            a += __shfl_xor_sync(0xffffffffu, a, 2);
            r2 = a;
        }
        {
            const float* p = base0 + 3 * HW;
            float a = wxwb * (wy.x * p[ro.x] + wy.y * p[ro.y] +
                              wy.z * p[ro.z] + wy.w * p[ro.w]);
            a += __shfl_xor_sync(0xffffffffu, a, 1);
            a += __shfl_xor_sync(0xffffffffu, a, 2);
            r3 = a;
        }

        if (writer) {
            const int o = ph * OUTP + pw;
            out_g[0 * BINS + o] = r0 * 0.25f;
            out_g[1 * BINS + o] = r1 * 0.25f;
            out_g[2 * BINS + o] = r2 * 0.25f;
            out_g[3 * BINS + o] = r3 * 0.25f;
        }
    }
}

extern "C" void kernel_launch(void* const* d_in, const int* in_sizes, int n_in,
                              void* d_out, int out_size) {
    const float* f0    = (const float*)d_in[0];
    const float* f1    = (const float*)d_in[1];
    const float* f2    = (const float*)d_in[2];
    const float* f3    = (const float*)d_in[3];
    const float* boxes = (const float*)d_in[4];
    float* out = (float*)d_out;

    roi_pooler_kernel<<<512 * NGROUPS, THREADS>>>(f0, f1, f2, f3, boxes, out);
}

// round 7
// speedup vs baseline: 8.6617x; 1.0841x over previous
#include <cuda_runtime.h>
#include <cstdint>

#define OUTP 7
#define CCH 256
#define NS 14                        // samples per axis
#define BINS 49
#define OUT_PER_BOX (CCH * BINS)     // 12544
#define CH_PER_CTA 32
#define NGROUPS (CCH / CH_PER_CTA)   // 8
#define THREADS 256
#define NWARPS (THREADS / 32)        // 8 warps -> 8*4 = 32 channels

__global__ __launch_bounds__(THREADS) void roi_pooler_kernel(
    const float* __restrict__ f0, const float* __restrict__ f1,
    const float* __restrict__ f2, const float* __restrict__ f3,
    const float* __restrict__ boxes, float* __restrict__ out)
{
    // Per-ph packed y-params: 4 row offsets (already *W) and 4 weights
    __shared__ int4   s_ro[OUTP];
    __shared__ float4 s_wy[OUTP];
    // Per-lane x-tap: column index and x-weight (validity folded in)
    __shared__ int    s_col[28];
    __shared__ float  s_wxw[28];
    __shared__ float  s_x1, s_y1, s_bw, s_bh, s_Hf, s_Wf;
    __shared__ int    s_W, s_HW;
    __shared__ const float* s_base;

    const int blk  = blockIdx.x;             // [0, 512*NGROUPS)
    const int n    = blk >> 3;               // box index [0,512)
    const int g    = blk & (NGROUPS - 1);    // channel group [0,8)
    const int tid  = threadIdx.x;
    const int lane = tid & 31;
    const int wid  = tid >> 5;

    // ---- A: box geometry ----
    if (tid == 0) {
        const int b = n >> 8;
        const float bx1 = boxes[n * 4 + 0];
        const float by1 = boxes[n * 4 + 1];
        const float bx2 = boxes[n * 4 + 2];
        const float by2 = boxes[n * 4 + 3];
        const float area = (bx2 - bx1) * (by2 - by1);
        float lvlf = floorf(4.0f + log2f(sqrtf(area) * (1.0f / 224.0f) + 1e-8f));
        lvlf = fminf(fmaxf(lvlf, 2.0f), 5.0f);
        const int lvl = (int)lvlf - 2;

        int H, W; float scale; const float* fp;
        switch (lvl) {
            case 0:  H = 200; W = 200; scale = 0.25f;    fp = f0; break;
            case 1:  H = 100; W = 100; scale = 0.125f;   fp = f1; break;
            case 2:  H = 50;  W = 50;  scale = 0.0625f;  fp = f2; break;
            default: H = 25;  W = 25;  scale = 0.03125f; fp = f3; break;
        }
        const float x1s = bx1 * scale, y1s = by1 * scale;
        const float x2s = bx2 * scale, y2s = by2 * scale;
        s_x1 = x1s;  s_y1 = y1s;
        s_bw = fmaxf(x2s - x1s, 1.0f) * (1.0f / OUTP);
        s_bh = fmaxf(y2s - y1s, 1.0f) * (1.0f / OUTP);
        s_Hf = (float)H;  s_Wf = (float)W;
        s_W = W;  s_HW = H * W;
        s_base = fp + ((size_t)b * CCH + (size_t)g * CH_PER_CTA) * H * W;
    }
    __syncthreads();

    // ---- B: 28 sample preps (torchvision ROIAlign aligned=False) ----
    if (tid < 2 * NS) {
        const bool is_y = tid < NS;
        const int  i    = is_y ? tid : tid - NS;
        const int  p    = i >> 1;
        const int  s    = i & 1;
        const float gg  = (float)p + ((float)s + 0.5f) * 0.5f;
        const float coord = is_y ? (s_y1 + s_bh * gg) : (s_x1 + s_bw * gg);
        const float lim   = is_y ? s_Hf : s_Wf;

        const float v  = (coord > -1.0f && coord < lim) ? 1.0f : 0.0f;
        float cc  = fmaxf(coord, 0.0f);
        float low = floorf(cc);
        const float cap = lim - 1.0f;
        const bool at_edge = (low >= cap);
        low = fminf(low, cap);
        const float high = fminf(low + 1.0f, cap);
        if (at_edge) cc = low;
        const float frac = cc - low;
        const float w0 = (1.0f - frac) * v;
        const float w1 = frac * v;

        if (is_y) {
            const int W = s_W;
            int*   rop = (int*)s_ro;
            float* wyp = (float*)s_wy;
            rop[4 * (i >> 1) + 2 * (i & 1) + 0] = (int)low  * W;
            rop[4 * (i >> 1) + 2 * (i & 1) + 1] = (int)high * W;
            wyp[4 * (i >> 1) + 2 * (i & 1) + 0] = w0;
            wyp[4 * (i >> 1) + 2 * (i & 1) + 1] = w1;
        } else {
            // fold the final *0.25 (subsample mean) into the x weights
            s_col[2 * i + 0] = (int)low;
            s_col[2 * i + 1] = (int)high;
            s_wxw[2 * i + 0] = w0 * 0.25f;
            s_wxw[2 * i + 1] = w1 * 0.25f;
        }
    }
    __syncthreads();

    // ---- C: compute. warp = 4 channels; lanes = 28 x-taps (4 per bin pw).
    // Lanes 28..31 duplicate tap 27 with zero weight: their addresses stay
    // inside the ROI column span (no extra 128B sector per LDG).
    const int   laneT = (lane < 28) ? lane : 27;
    const int   colb  = s_col[laneT];
    const float wxwb  = (lane < 28) ? s_wxw[laneT] : 0.0f;
    const int   HW    = s_HW;
    const float* const base0 = s_base + (size_t)(wid * 4) * HW + colb;
    float* const out_g = out + (size_t)n * OUT_PER_BOX
                             + (size_t)g * CH_PER_CTA * BINS
                             + (size_t)(wid * 4) * BINS;

    const bool writer = ((lane & 3) == 0) && (lane < 28);
    const int  pw     = lane >> 2;

    #pragma unroll 2
    for (int ph = 0; ph < OUTP; ++ph) {
        const int4   ro = s_ro[ph];
        const float4 wy = s_wy[ph];

        // batch all 16 loads (4 channels x 4 row taps) for MLP
        const float* p0 = base0;
        const float* p1 = base0 + HW;
        const float* p2 = base0 + 2 * HW;
        const float* p3 = base0 + 3 * HW;
        const float v00 = p0[ro.x], v01 = p0[ro.y], v02 = p0[ro.z], v03 = p0[ro.w];
        const float v10 = p1[ro.x], v11 = p1[ro.y], v12 = p1[ro.z], v13 = p1[ro.w];
        const float v20 = p2[ro.x], v21 = p2[ro.y], v22 = p2[ro.z], v23 = p2[ro.w];
        const float v30 = p3[ro.x], v31 = p3[ro.y], v32 = p3[ro.z], v33 = p3[ro.w];

        float a0 = wxwb * (wy.x * v00 + wy.y * v01 + wy.z * v02 + wy.w * v03);
        float a1 = wxwb * (wy.x * v10 + wy.y * v11 + wy.z * v12 + wy.w * v13);
        float a2 = wxwb * (wy.x * v20 + wy.y * v21 + wy.z * v22 + wy.w * v23);
        float a3 = wxwb * (wy.x * v30 + wy.y * v31 + wy.z * v32 + wy.w * v33);

        a0 += __shfl_xor_sync(0xffffffffu, a0, 1);
        a1 += __shfl_xor_sync(0xffffffffu, a1, 1);
        a2 += __shfl_xor_sync(0xffffffffu, a2, 1);
        a3 += __shfl_xor_sync(0xffffffffu, a3, 1);
        a0 += __shfl_xor_sync(0xffffffffu, a0, 2);
        a1 += __shfl_xor_sync(0xffffffffu, a1, 2);
        a2 += __shfl_xor_sync(0xffffffffu, a2, 2);
        a3 += __shfl_xor_sync(0xffffffffu, a3, 2);

        if (writer) {
            const int o = ph * OUTP + pw;
            out_g[0 * BINS + o] = a0;
            out_g[1 * BINS + o] = a1;
            out_g[2 * BINS + o] = a2;
            out_g[3 * BINS + o] = a3;
        }
    }
}

extern "C" void kernel_launch(void* const* d_in, const int* in_sizes, int n_in,
                              void* d_out, int out_size) {
    const float* f0    = (const float*)d_in[0];
    const float* f1    = (const float*)d_in[1];
    const float* f2    = (const float*)d_in[2];
    const float* f3    = (const float*)d_in[3];
    const float* boxes = (const float*)d_in[4];
    float* out = (float*)d_out;

    roi_pooler_kernel<<<512 * NGROUPS, THREADS>>>(f0, f1, f2, f3, boxes, out);
}